// round 1
// baseline (speedup 1.0000x reference)
#include <cuda_runtime.h>
#include <math.h>

#define F 128
#define MAXN 50176   // >= 50000, padded

// ---------------- scratch (no allocations allowed) ----------------
__device__ float g_h[(size_t)MAXN * F];     // GEMM output (x@W)
__device__ float g_agg[(size_t)MAXN * F];   // scatter accumulator / layer output
__device__ float g_deg[MAXN];
__device__ float g_dinv[MAXN];
__device__ float g_pool[F];

// ---------------- degree / norm ----------------
__global__ void k_zero_deg(int n) {
    int i = blockIdx.x * blockDim.x + threadIdx.x;
    if (i < n) g_deg[i] = 0.f;
    if (i < F) g_pool[i] = 0.f;
}

__global__ void k_count(const int* __restrict__ dst, int E) {
    int i = blockIdx.x * blockDim.x + threadIdx.x;
    if (i < E) atomicAdd(&g_deg[dst[i]], 1.0f);
}

__global__ void k_dinv(int n) {
    int i = blockIdx.x * blockDim.x + threadIdx.x;
    if (i < n) g_dinv[i] = rsqrtf(g_deg[i] + 1.0f);  // +1 self loop, always > 0
}

// ---------------- GEMM: C[n,128] = A[n,128] @ W[128,128] ----------------
// 128x128 output tile per block, 256 threads, 8x8 register micro-tile, K-tiles of 16.
__global__ __launch_bounds__(256) void k_gemm(const float* __restrict__ A,
                                              const float* __restrict__ W,
                                              float* __restrict__ C, int n) {
    __shared__ float sA[16 * 128];  // transposed: sA[k][row]
    __shared__ float sW[16 * 128];  // sW[k][col]
    const int t = threadIdx.x;
    const int tx = t & 15;   // col group (8 cols)
    const int ty = t >> 4;   // row group (8 rows)
    const int row0 = blockIdx.x * 128;

    float acc[8][8];
#pragma unroll
    for (int i = 0; i < 8; i++)
#pragma unroll
        for (int j = 0; j < 8; j++) acc[i][j] = 0.f;

    for (int kt = 0; kt < 128; kt += 16) {
        // Load A tile (128 rows x 16 k), transpose into sA[k][row].
        {
            int r  = t >> 2;      // 0..63
            int kv = t & 3;       // float4 index within the 16-wide k tile
            float4 v0 = make_float4(0.f, 0.f, 0.f, 0.f);
            float4 v1 = v0;
            if (row0 + r      < n) v0 = *(const float4*)(A + (size_t)(row0 + r) * 128 + kt + kv * 4);
            if (row0 + r + 64 < n) v1 = *(const float4*)(A + (size_t)(row0 + r + 64) * 128 + kt + kv * 4);
            sA[(kv * 4 + 0) * 128 + r] = v0.x;
            sA[(kv * 4 + 1) * 128 + r] = v0.y;
            sA[(kv * 4 + 2) * 128 + r] = v0.z;
            sA[(kv * 4 + 3) * 128 + r] = v0.w;
            sA[(kv * 4 + 0) * 128 + r + 64] = v1.x;
            sA[(kv * 4 + 1) * 128 + r + 64] = v1.y;
            sA[(kv * 4 + 2) * 128 + r + 64] = v1.z;
            sA[(kv * 4 + 3) * 128 + r + 64] = v1.w;
        }
        // Load W tile (16 k x 128 cols).
        {
            int kr = t >> 5;      // 0..7
            int c4 = t & 31;      // float4 col index
            float4 w0 = *(const float4*)(W + (size_t)(kt + kr) * 128 + c4 * 4);
            float4 w1 = *(const float4*)(W + (size_t)(kt + kr + 8) * 128 + c4 * 4);
            *(float4*)(sW + kr * 128 + c4 * 4) = w0;
            *(float4*)(sW + (kr + 8) * 128 + c4 * 4) = w1;
        }
        __syncthreads();

#pragma unroll
        for (int k = 0; k < 16; k++) {
            float a[8], w[8];
            *(float4*)(a)     = *(const float4*)(sA + k * 128 + ty * 8);
            *(float4*)(a + 4) = *(const float4*)(sA + k * 128 + ty * 8 + 4);
            *(float4*)(w)     = *(const float4*)(sW + k * 128 + tx * 8);
            *(float4*)(w + 4) = *(const float4*)(sW + k * 128 + tx * 8 + 4);
#pragma unroll
            for (int i = 0; i < 8; i++)
#pragma unroll
                for (int j = 0; j < 8; j++) acc[i][j] += a[i] * w[j];
        }
        __syncthreads();
    }

#pragma unroll
    for (int i = 0; i < 8; i++) {
        int row = row0 + ty * 8 + i;
        if (row < n) {
            float4 o0 = make_float4(acc[i][0], acc[i][1], acc[i][2], acc[i][3]);
            float4 o1 = make_float4(acc[i][4], acc[i][5], acc[i][6], acc[i][7]);
            *(float4*)(C + (size_t)row * 128 + tx * 8)     = o0;
            *(float4*)(C + (size_t)row * 128 + tx * 8 + 4) = o1;
        }
    }
}

// ---------------- zero agg ----------------
__global__ void k_zero_agg(int n) {
    int total = n * 32;  // float4 count
    for (int i = blockIdx.x * blockDim.x + threadIdx.x; i < total; i += gridDim.x * blockDim.x)
        ((float4*)g_agg)[i] = make_float4(0.f, 0.f, 0.f, 0.f);
}

// ---------------- edge scatter: agg[dst] += h[src] * norm ----------------
// One warp per edge, lane handles 4 consecutive feats; vector red.global.add.v4.f32.
__global__ __launch_bounds__(256) void k_scatter(const int* __restrict__ src,
                                                 const int* __restrict__ dst, int E) {
    int gid = blockIdx.x * blockDim.x + threadIdx.x;
    int e = gid >> 5;
    int lane = gid & 31;
    if (e >= E) return;
    int s = __ldg(src + e);
    int d = __ldg(dst + e);
    float norm = g_dinv[s] * g_dinv[d];
    float4 v = *(const float4*)(g_h + (size_t)s * 128 + lane * 4);
    v.x *= norm; v.y *= norm; v.z *= norm; v.w *= norm;
    float* p = g_agg + (size_t)d * 128 + lane * 4;
    asm volatile("red.global.add.v4.f32 [%0], {%1,%2,%3,%4};"
                 :: "l"(p), "f"(v.x), "f"(v.y), "f"(v.z), "f"(v.w) : "memory");
}

// ---------------- self-loop + bias + relu (in place on g_agg) ----------------
__global__ void k_bias_relu(const float* __restrict__ b, int n) {
    int total = n * 32;  // float4 count
    for (int i = blockIdx.x * blockDim.x + threadIdx.x; i < total; i += gridDim.x * blockDim.x) {
        int f4 = i & 31;
        int row = i >> 5;
        float di = g_dinv[row];
        float d2 = di * di;
        float4 a  = ((float4*)g_agg)[i];
        float4 hh = ((const float4*)g_h)[i];
        float4 bb = ((const float4*)b)[f4];
        a.x = fmaxf(a.x + hh.x * d2 + bb.x, 0.f);
        a.y = fmaxf(a.y + hh.y * d2 + bb.y, 0.f);
        a.z = fmaxf(a.z + hh.z * d2 + bb.z, 0.f);
        a.w = fmaxf(a.w + hh.w * d2 + bb.w, 0.f);
        ((float4*)g_agg)[i] = a;
    }
}

// ---------------- mean pool (sum; divide in mlp) ----------------
__global__ __launch_bounds__(128) void k_pool(int n) {
    int f = threadIdx.x;
    int r0 = blockIdx.x * 64;
    int r1 = min(r0 + 64, n);
    float acc = 0.f;
    for (int r = r0; r < r1; r++) acc += g_agg[(size_t)r * 128 + f];
    atomicAdd(&g_pool[f], acc);
}

// ---------------- MLP tail (single block) ----------------
__global__ __launch_bounds__(128) void k_mlp(const float* __restrict__ w1, const float* __restrict__ b1,
                                             const float* __restrict__ w2, const float* __restrict__ b2,
                                             const float* __restrict__ w3, const float* __restrict__ b3,
                                             const float* __restrict__ w4, const float* __restrict__ b4,
                                             float* __restrict__ out, int n) {
    __shared__ float v[128], u[128];
    __shared__ float red[4];
    int t = threadIdx.x;
    v[t] = g_pool[t] / (float)n;
    __syncthreads();

    float acc = b1[t];
    for (int k = 0; k < 128; k++) acc += v[k] * w1[k * 128 + t];
    u[t] = fmaxf(acc, 0.f);
    __syncthreads();

    acc = b2[t];
    for (int k = 0; k < 128; k++) acc += u[k] * w2[k * 128 + t];
    v[t] = acc;
    __syncthreads();

    acc = b3[t];
    for (int k = 0; k < 128; k++) acc += v[k] * w3[k * 128 + t];
    u[t] = fmaxf(acc, 0.f);
    __syncthreads();

    float p = u[t] * w4[t];
#pragma unroll
    for (int o = 16; o; o >>= 1) p += __shfl_down_sync(0xffffffffu, p, o);
    if ((t & 31) == 0) red[t >> 5] = p;
    __syncthreads();
    if (t == 0) {
        float s = red[0] + red[1] + red[2] + red[3] + b4[0];
        out[0] = 1.f / (1.f + expf(-s));
    }
}

// ---------------- launch ----------------
extern "C" void kernel_launch(void* const* d_in, const int* in_sizes, int n_in,
                              void* d_out, int out_size) {
    const float* x    = (const float*)d_in[0];
    const int*   ei   = (const int*)d_in[1];
    const float* c1w  = (const float*)d_in[2];
    const float* c1b  = (const float*)d_in[3];
    const float* c2w  = (const float*)d_in[4];
    const float* c2b  = (const float*)d_in[5];
    const float* f1w1 = (const float*)d_in[6];
    const float* f1b1 = (const float*)d_in[7];
    const float* f1w2 = (const float*)d_in[8];
    const float* f1b2 = (const float*)d_in[9];
    const float* f2w1 = (const float*)d_in[10];
    const float* f2b1 = (const float*)d_in[11];
    const float* f2w2 = (const float*)d_in[12];
    const float* f2b2 = (const float*)d_in[13];

    int n = in_sizes[0] / F;
    int E = in_sizes[1] / 2;
    const int* src = ei;
    const int* dst = ei + E;

    float* h   = nullptr;
    float* agg = nullptr;
    cudaGetSymbolAddress((void**)&h,   g_h);
    cudaGetSymbolAddress((void**)&agg, g_agg);

    int tb = 256;
    int gN    = (n + tb - 1) / tb;
    int gE    = (E + tb - 1) / tb;
    int gGemm = (n + 127) / 128;
    int gElem = (n * 32 + tb - 1) / tb;
    long long scatterThreads = (long long)E * 32;
    int gScat = (int)((scatterThreads + tb - 1) / tb);
    int gPool = (n + 63) / 64;

    // degrees + norm
    k_zero_deg<<<gN, tb>>>(n);
    k_count<<<gE, tb>>>(dst, E);
    k_dinv<<<gN, tb>>>(n);

    // conv1
    k_gemm<<<gGemm, 256>>>(x, c1w, h, n);
    k_zero_agg<<<gElem, tb>>>(n);
    k_scatter<<<gScat, tb>>>(src, dst, E);
    k_bias_relu<<<gElem, tb>>>(c1b, n);

    // conv2 (input = g_agg, output h, re-aggregate into g_agg)
    k_gemm<<<gGemm, 256>>>(agg, c2w, h, n);
    k_zero_agg<<<gElem, tb>>>(n);
    k_scatter<<<gScat, tb>>>(src, dst, E);
    k_bias_relu<<<gElem, tb>>>(c2b, n);

    // pool + MLP tail
    k_pool<<<gPool, 128>>>(n);
    k_mlp<<<1, 128>>>(f1w1, f1b1, f1w2, f1b2, f2w1, f2b1, f2w2, f2b2,
                      (float*)d_out, n);
}

// round 2
// speedup vs baseline: 1.6087x; 1.6087x over previous
#include <cuda_runtime.h>
#include <math.h>

#define F 128
#define MAXN 50176    // >= 50000
#define CAP 128       // max in-degree bucket (Poisson(16): P(deg>128) ~ 0)

// ---------------- scratch (no allocations allowed) ----------------
__device__ float g_h[(size_t)MAXN * F];     // GEMM output, pre-scaled by dinv[row]
__device__ float g_agg[(size_t)MAXN * F];   // layer output
__device__ float g_dinv[MAXN];
__device__ int   g_cnt[MAXN];               // in-degree (excl. self loop)
__device__ int   g_csr[(size_t)MAXN * CAP]; // bucketed neighbor lists (src ids)
__device__ float g_pool[F];

// ---------------- init: zero counts + pool ----------------
__global__ void k_init(int n) {
    int i = blockIdx.x * blockDim.x + threadIdx.x;
    if (i < n) g_cnt[i] = 0;
    if (i < F) g_pool[i] = 0.f;
}

// ---------------- CSR bucket fill ----------------
__global__ void k_fill(const int* __restrict__ src, const int* __restrict__ dst, int E) {
    int e = blockIdx.x * blockDim.x + threadIdx.x;
    if (e >= E) return;
    int d = dst[e];
    int pos = atomicAdd(&g_cnt[d], 1);
    if (pos < CAP) g_csr[(size_t)d * CAP + pos] = src[e];
}

// ---------------- dinv = rsqrt(deg + 1) ----------------
__global__ void k_dinv(int n) {
    int i = blockIdx.x * blockDim.x + threadIdx.x;
    if (i < n) g_dinv[i] = rsqrtf((float)g_cnt[i] + 1.0f);
}

// ---------------- GEMM: C[n,128] = (A[n,128] @ W[128,128]) * dinv[row] ----------------
// 128x128 output tile per block, 256 threads, 8x8 register micro-tile, K-tiles of 16.
__global__ __launch_bounds__(256) void k_gemm(const float* __restrict__ A,
                                              const float* __restrict__ W,
                                              float* __restrict__ C, int n) {
    __shared__ float sA[16 * 128];  // transposed: sA[k][row]
    __shared__ float sW[16 * 128];  // sW[k][col]
    const int t = threadIdx.x;
    const int tx = t & 15;   // col group (8 cols)
    const int ty = t >> 4;   // row group (8 rows)
    const int row0 = blockIdx.x * 128;

    float acc[8][8];
#pragma unroll
    for (int i = 0; i < 8; i++)
#pragma unroll
        for (int j = 0; j < 8; j++) acc[i][j] = 0.f;

    for (int kt = 0; kt < 128; kt += 16) {
        {
            int r  = t >> 2;
            int kv = t & 3;
            float4 v0 = make_float4(0.f, 0.f, 0.f, 0.f);
            float4 v1 = v0;
            if (row0 + r      < n) v0 = *(const float4*)(A + (size_t)(row0 + r) * 128 + kt + kv * 4);
            if (row0 + r + 64 < n) v1 = *(const float4*)(A + (size_t)(row0 + r + 64) * 128 + kt + kv * 4);
            sA[(kv * 4 + 0) * 128 + r] = v0.x;
            sA[(kv * 4 + 1) * 128 + r] = v0.y;
            sA[(kv * 4 + 2) * 128 + r] = v0.z;
            sA[(kv * 4 + 3) * 128 + r] = v0.w;
            sA[(kv * 4 + 0) * 128 + r + 64] = v1.x;
            sA[(kv * 4 + 1) * 128 + r + 64] = v1.y;
            sA[(kv * 4 + 2) * 128 + r + 64] = v1.z;
            sA[(kv * 4 + 3) * 128 + r + 64] = v1.w;
        }
        {
            int kr = t >> 5;
            int c4 = t & 31;
            float4 w0 = *(const float4*)(W + (size_t)(kt + kr) * 128 + c4 * 4);
            float4 w1 = *(const float4*)(W + (size_t)(kt + kr + 8) * 128 + c4 * 4);
            *(float4*)(sW + kr * 128 + c4 * 4) = w0;
            *(float4*)(sW + (kr + 8) * 128 + c4 * 4) = w1;
        }
        __syncthreads();

#pragma unroll
        for (int k = 0; k < 16; k++) {
            float a[8], w[8];
            *(float4*)(a)     = *(const float4*)(sA + k * 128 + ty * 8);
            *(float4*)(a + 4) = *(const float4*)(sA + k * 128 + ty * 8 + 4);
            *(float4*)(w)     = *(const float4*)(sW + k * 128 + tx * 8);
            *(float4*)(w + 4) = *(const float4*)(sW + k * 128 + tx * 8 + 4);
#pragma unroll
            for (int i = 0; i < 8; i++)
#pragma unroll
                for (int j = 0; j < 8; j++) acc[i][j] += a[i] * w[j];
        }
        __syncthreads();
    }

#pragma unroll
    for (int i = 0; i < 8; i++) {
        int row = row0 + ty * 8 + i;
        if (row < n) {
            float di = g_dinv[row];
            float4 o0 = make_float4(acc[i][0] * di, acc[i][1] * di, acc[i][2] * di, acc[i][3] * di);
            float4 o1 = make_float4(acc[i][4] * di, acc[i][5] * di, acc[i][6] * di, acc[i][7] * di);
            *(float4*)(C + (size_t)row * 128 + tx * 8)     = o0;
            *(float4*)(C + (size_t)row * 128 + tx * 8 + 4) = o1;
        }
    }
}

// ---------------- gather-aggregate + self-loop + dinv + bias + relu ----------------
// One warp per node; lane handles float4 (4 feats). out = relu(dinv*(Σ hs[s] + hs[d]) + b)
__global__ __launch_bounds__(256) void k_aggregate(const float* __restrict__ b,
                                                   float* __restrict__ out, int n) {
    int gid  = blockIdx.x * blockDim.x + threadIdx.x;
    int node = gid >> 5;
    int lane = gid & 31;
    if (node >= n) return;

    const float4* hs = (const float4*)g_h;
    float4 acc = hs[(size_t)node * 32 + lane];        // self-loop term hs[d]
    int deg = g_cnt[node];
    if (deg > CAP) deg = CAP;
    const int* lst = g_csr + (size_t)node * CAP;

    int i = 0;
    for (; i + 4 <= deg; i += 4) {
        int s0 = lst[i], s1 = lst[i + 1], s2 = lst[i + 2], s3 = lst[i + 3];
        float4 v0 = hs[(size_t)s0 * 32 + lane];
        float4 v1 = hs[(size_t)s1 * 32 + lane];
        float4 v2 = hs[(size_t)s2 * 32 + lane];
        float4 v3 = hs[(size_t)s3 * 32 + lane];
        acc.x += v0.x + v1.x + v2.x + v3.x;
        acc.y += v0.y + v1.y + v2.y + v3.y;
        acc.z += v0.z + v1.z + v2.z + v3.z;
        acc.w += v0.w + v1.w + v2.w + v3.w;
    }
    for (; i < deg; i++) {
        int s = lst[i];
        float4 v = hs[(size_t)s * 32 + lane];
        acc.x += v.x; acc.y += v.y; acc.z += v.z; acc.w += v.w;
    }

    float di = g_dinv[node];
    float4 bb = ((const float4*)b)[lane];
    acc.x = fmaxf(acc.x * di + bb.x, 0.f);
    acc.y = fmaxf(acc.y * di + bb.y, 0.f);
    acc.z = fmaxf(acc.z * di + bb.z, 0.f);
    acc.w = fmaxf(acc.w * di + bb.w, 0.f);
    ((float4*)out)[(size_t)node * 32 + lane] = acc;
}

// ---------------- mean pool (sum; divide in mlp) ----------------
__global__ __launch_bounds__(128) void k_pool(int n) {
    int f = threadIdx.x;
    int r0 = blockIdx.x * 64;
    int r1 = min(r0 + 64, n);
    float acc = 0.f;
    for (int r = r0; r < r1; r++) acc += g_agg[(size_t)r * 128 + f];
    atomicAdd(&g_pool[f], acc);
}

// ---------------- MLP tail (single block) ----------------
__global__ __launch_bounds__(128) void k_mlp(const float* __restrict__ w1, const float* __restrict__ b1,
                                             const float* __restrict__ w2, const float* __restrict__ b2,
                                             const float* __restrict__ w3, const float* __restrict__ b3,
                                             const float* __restrict__ w4, const float* __restrict__ b4,
                                             float* __restrict__ out, int n) {
    __shared__ float v[128], u[128];
    __shared__ float red[4];
    int t = threadIdx.x;
    v[t] = g_pool[t] / (float)n;
    __syncthreads();

    float acc = b1[t];
    for (int k = 0; k < 128; k++) acc += v[k] * w1[k * 128 + t];
    u[t] = fmaxf(acc, 0.f);
    __syncthreads();

    acc = b2[t];
    for (int k = 0; k < 128; k++) acc += u[k] * w2[k * 128 + t];
    v[t] = acc;
    __syncthreads();

    acc = b3[t];
    for (int k = 0; k < 128; k++) acc += v[k] * w3[k * 128 + t];
    u[t] = fmaxf(acc, 0.f);
    __syncthreads();

    float p = u[t] * w4[t];
#pragma unroll
    for (int o = 16; o; o >>= 1) p += __shfl_down_sync(0xffffffffu, p, o);
    if ((t & 31) == 0) red[t >> 5] = p;
    __syncthreads();
    if (t == 0) {
        float s = red[0] + red[1] + red[2] + red[3] + b4[0];
        out[0] = 1.f / (1.f + expf(-s));
    }
}

// ---------------- launch ----------------
extern "C" void kernel_launch(void* const* d_in, const int* in_sizes, int n_in,
                              void* d_out, int out_size) {
    const float* x    = (const float*)d_in[0];
    const int*   ei   = (const int*)d_in[1];
    const float* c1w  = (const float*)d_in[2];
    const float* c1b  = (const float*)d_in[3];
    const float* c2w  = (const float*)d_in[4];
    const float* c2b  = (const float*)d_in[5];
    const float* f1w1 = (const float*)d_in[6];
    const float* f1b1 = (const float*)d_in[7];
    const float* f1w2 = (const float*)d_in[8];
    const float* f1b2 = (const float*)d_in[9];
    const float* f2w1 = (const float*)d_in[10];
    const float* f2b1 = (const float*)d_in[11];
    const float* f2w2 = (const float*)d_in[12];
    const float* f2b2 = (const float*)d_in[13];

    int n = in_sizes[0] / F;
    int E = in_sizes[1] / 2;
    const int* src = ei;
    const int* dst = ei + E;

    float* h   = nullptr;
    float* agg = nullptr;
    cudaGetSymbolAddress((void**)&h,   g_h);
    cudaGetSymbolAddress((void**)&agg, g_agg);

    int tb = 256;
    int gN    = (n + tb - 1) / tb;
    int gE    = (E + tb - 1) / tb;
    int gGemm = (n + 127) / 128;
    int gAgg  = (n * 32 + tb - 1) / tb;   // one warp per node
    int gPool = (n + 63) / 64;

    // graph prep: degree buckets + dinv
    k_init<<<gN, tb>>>(n);
    k_fill<<<gE, tb>>>(src, dst, E);
    k_dinv<<<gN, tb>>>(n);

    // conv1: h = (x@W1)*dinv ; agg = relu(dinv*(gather-sum + self) + b1)
    k_gemm<<<gGemm, 256>>>(x, c1w, h, n);
    k_aggregate<<<gAgg, tb>>>(c1b, agg, n);

    // conv2
    k_gemm<<<gGemm, 256>>>(agg, c2w, h, n);
    k_aggregate<<<gAgg, tb>>>(c2b, agg, n);

    // pool + MLP tail
    k_pool<<<gPool, 128>>>(n);
    k_mlp<<<1, 128>>>(f1w1, f1b1, f1w2, f1b2, f2w1, f2b1, f2w2, f2b2,
                      (float*)d_out, n);
}

// round 3
// speedup vs baseline: 2.2854x; 1.4206x over previous
#include <cuda_runtime.h>
#include <math.h>
#include <stdint.h>

#define F 128
#define MAXN 50176    // >= 50000
#define CAP 128       // max in-degree bucket (Poisson(16): P(deg>128) ~ 0)

// ---------------- scratch (no allocations allowed) ----------------
__device__ float g_h[(size_t)MAXN * F];     // GEMM output, pre-scaled by dinv[row]
__device__ float g_agg[(size_t)MAXN * F];   // layer output
__device__ float g_dinv[MAXN];
__device__ int   g_cnt[MAXN];               // in-degree (excl. self loop)
__device__ int   g_csr[(size_t)MAXN * CAP]; // bucketed neighbor lists (src ids)
__device__ float g_pool[F];

// ---------------- init: zero counts + pool ----------------
__global__ void k_init(int n) {
    int i = blockIdx.x * blockDim.x + threadIdx.x;
    if (i < n) g_cnt[i] = 0;
    if (i < F) g_pool[i] = 0.f;
}

// ---------------- CSR bucket fill ----------------
__global__ void k_fill(const int* __restrict__ src, const int* __restrict__ dst, int E) {
    int e = blockIdx.x * blockDim.x + threadIdx.x;
    if (e >= E) return;
    int d = dst[e];
    int pos = atomicAdd(&g_cnt[d], 1);
    if (pos < CAP) g_csr[(size_t)d * CAP + pos] = src[e];
}

// ---------------- dinv = rsqrt(deg + 1) ----------------
__global__ void k_dinv(int n) {
    int i = blockIdx.x * blockDim.x + threadIdx.x;
    if (i < n) g_dinv[i] = rsqrtf((float)g_cnt[i] + 1.0f);
}

// ---------------- tf32 tensor-core GEMM ----------------
// C[n,128] = (A[n,128] @ W[128,128]) * dinv[row]
// 128x128 block tile, 256 threads = 8 warps (4 row x 2 col), warp tile 32x64,
// mma.sync.m16n8k8 tf32. K tiled by 32.
// sA stride 36 floats  (36 mod 32 = 4  -> frag-load banks 4g+c, conflict-free)
// sW stride 136 floats (136 mod 32 = 8 -> frag-load banks 8c+g, conflict-free)
#define SA_STRIDE 36
#define SW_STRIDE 136

__device__ __forceinline__ uint32_t f2tf32(float x) {
    uint32_t r;
    asm("cvt.rna.tf32.f32 %0, %1;" : "=r"(r) : "f"(x));
    return r;
}

__global__ __launch_bounds__(256) void k_gemm_tc(const float* __restrict__ A,
                                                 const float* __restrict__ W,
                                                 float* __restrict__ C, int n) {
    __shared__ float sA[128 * SA_STRIDE];
    __shared__ float sW[32 * SW_STRIDE];

    const int t    = threadIdx.x;
    const int lane = t & 31;
    const int w    = t >> 5;
    const int wr   = w & 3;          // warp row (0..3) -> 32 rows each
    const int wc   = w >> 2;         // warp col (0..1) -> 64 cols each
    const int g    = lane >> 2;      // groupID (0..7)
    const int c    = lane & 3;       // threadID_in_group (0..3)
    const int blockRow = blockIdx.x * 128;

    float d[2][8][4];
#pragma unroll
    for (int mt = 0; mt < 2; mt++)
#pragma unroll
        for (int nt = 0; nt < 8; nt++)
#pragma unroll
            for (int i = 0; i < 4; i++) d[mt][nt][i] = 0.f;

    const uint32_t* sAu = (const uint32_t*)sA;
    const uint32_t* sWu = (const uint32_t*)sW;

    for (int kt = 0; kt < 4; kt++) {
        // ---- fill A tile: 128 rows x 32 k, tf32-converted, stride 36 ----
#pragma unroll
        for (int j = 0; j < 4; j++) {
            int idx = t + 256 * j;          // 0..1023
            int row = idx >> 3;             // 0..127
            int kq  = idx & 7;              // float4 within 32-k tile
            float4 v = make_float4(0.f, 0.f, 0.f, 0.f);
            if (blockRow + row < n)
                v = __ldg((const float4*)(A + (size_t)(blockRow + row) * 128 + kt * 32 + kq * 4));
            float4 o;
            o.x = __uint_as_float(f2tf32(v.x));
            o.y = __uint_as_float(f2tf32(v.y));
            o.z = __uint_as_float(f2tf32(v.z));
            o.w = __uint_as_float(f2tf32(v.w));
            *(float4*)(sA + row * SA_STRIDE + kq * 4) = o;   // byte addr row*144+16kq: 16B aligned, conflict-free
        }
        // ---- fill W tile: 32 k x 128 n, tf32-converted, stride 136 ----
#pragma unroll
        for (int j = 0; j < 4; j++) {
            int idx = t + 256 * j;          // 0..1023
            int n4  = idx & 31;             // float4 col
            int k   = idx >> 5;             // 0..31
            float4 v = __ldg((const float4*)(W + (size_t)(kt * 32 + k) * 128 + n4 * 4));
            float4 o;
            o.x = __uint_as_float(f2tf32(v.x));
            o.y = __uint_as_float(f2tf32(v.y));
            o.z = __uint_as_float(f2tf32(v.z));
            o.w = __uint_as_float(f2tf32(v.w));
            *(float4*)(sW + k * SW_STRIDE + n4 * 4) = o;     // byte addr k*544+16n4: aligned, conflict-free
        }
        __syncthreads();

#pragma unroll
        for (int kk = 0; kk < 4; kk++) {    // 4 ksteps of 8 within the 32-k tile
            uint32_t a[2][4];
#pragma unroll
            for (int mt = 0; mt < 2; mt++) {
                int r0 = wr * 32 + mt * 16;
                a[mt][0] = sAu[(r0 + g)     * SA_STRIDE + kk * 8 + c];
                a[mt][1] = sAu[(r0 + g + 8) * SA_STRIDE + kk * 8 + c];
                a[mt][2] = sAu[(r0 + g)     * SA_STRIDE + kk * 8 + c + 4];
                a[mt][3] = sAu[(r0 + g + 8) * SA_STRIDE + kk * 8 + c + 4];
            }
            uint32_t b[8][2];
#pragma unroll
            for (int nt = 0; nt < 8; nt++) {
                int n0 = wc * 64 + nt * 8;
                b[nt][0] = sWu[(kk * 8 + c)     * SW_STRIDE + n0 + g];
                b[nt][1] = sWu[(kk * 8 + c + 4) * SW_STRIDE + n0 + g];
            }
#pragma unroll
            for (int mt = 0; mt < 2; mt++)
#pragma unroll
                for (int nt = 0; nt < 8; nt++) {
                    asm volatile(
                        "mma.sync.aligned.m16n8k8.row.col.f32.tf32.tf32.f32 "
                        "{%0,%1,%2,%3}, {%4,%5,%6,%7}, {%8,%9}, {%0,%1,%2,%3};\n"
                        : "+f"(d[mt][nt][0]), "+f"(d[mt][nt][1]),
                          "+f"(d[mt][nt][2]), "+f"(d[mt][nt][3])
                        : "r"(a[mt][0]), "r"(a[mt][1]), "r"(a[mt][2]), "r"(a[mt][3]),
                          "r"(b[nt][0]), "r"(b[nt][1]));
                }
        }
        __syncthreads();
    }

    // ---- epilogue: scale by dinv[row], store float2 per (tile,half) ----
#pragma unroll
    for (int mt = 0; mt < 2; mt++) {
        int rowA = blockRow + wr * 32 + mt * 16 + g;
        int rowB = rowA + 8;
        float dA = (rowA < n) ? g_dinv[rowA] : 0.f;
        float dB = (rowB < n) ? g_dinv[rowB] : 0.f;
#pragma unroll
        for (int nt = 0; nt < 8; nt++) {
            int col = wc * 64 + nt * 8 + c * 2;
            if (rowA < n) {
                float2 o = make_float2(d[mt][nt][0] * dA, d[mt][nt][1] * dA);
                *(float2*)(C + (size_t)rowA * 128 + col) = o;
            }
            if (rowB < n) {
                float2 o = make_float2(d[mt][nt][2] * dB, d[mt][nt][3] * dB);
                *(float2*)(C + (size_t)rowB * 128 + col) = o;
            }
        }
    }
}

// ---------------- gather-aggregate + self-loop + dinv + bias + relu ----------------
// One warp per node; lane handles float4 (4 feats). out = relu(dinv*(Σ hs[s] + hs[d]) + b)
__global__ __launch_bounds__(256) void k_aggregate(const float* __restrict__ b,
                                                   float* __restrict__ out, int n) {
    int gid  = blockIdx.x * blockDim.x + threadIdx.x;
    int node = gid >> 5;
    int lane = gid & 31;
    if (node >= n) return;

    const float4* hs = (const float4*)g_h;
    float4 acc = hs[(size_t)node * 32 + lane];        // self-loop term hs[d]
    int deg = g_cnt[node];
    if (deg > CAP) deg = CAP;
    const int* lst = g_csr + (size_t)node * CAP;

    int i = 0;
    for (; i + 4 <= deg; i += 4) {
        int s0 = lst[i], s1 = lst[i + 1], s2 = lst[i + 2], s3 = lst[i + 3];
        float4 v0 = hs[(size_t)s0 * 32 + lane];
        float4 v1 = hs[(size_t)s1 * 32 + lane];
        float4 v2 = hs[(size_t)s2 * 32 + lane];
        float4 v3 = hs[(size_t)s3 * 32 + lane];
        acc.x += v0.x + v1.x + v2.x + v3.x;
        acc.y += v0.y + v1.y + v2.y + v3.y;
        acc.z += v0.z + v1.z + v2.z + v3.z;
        acc.w += v0.w + v1.w + v2.w + v3.w;
    }
    for (; i < deg; i++) {
        int s = lst[i];
        float4 v = hs[(size_t)s * 32 + lane];
        acc.x += v.x; acc.y += v.y; acc.z += v.z; acc.w += v.w;
    }

    float di = g_dinv[node];
    float4 bb = ((const float4*)b)[lane];
    acc.x = fmaxf(acc.x * di + bb.x, 0.f);
    acc.y = fmaxf(acc.y * di + bb.y, 0.f);
    acc.z = fmaxf(acc.z * di + bb.z, 0.f);
    acc.w = fmaxf(acc.w * di + bb.w, 0.f);
    ((float4*)out)[(size_t)node * 32 + lane] = acc;
}

// ---------------- mean pool (sum; divide in mlp) ----------------
__global__ __launch_bounds__(128) void k_pool(int n) {
    int f = threadIdx.x;
    int r0 = blockIdx.x * 64;
    int r1 = min(r0 + 64, n);
    float acc = 0.f;
    for (int r = r0; r < r1; r++) acc += g_agg[(size_t)r * 128 + f];
    atomicAdd(&g_pool[f], acc);
}

// ---------------- MLP tail (single block) ----------------
__global__ __launch_bounds__(128) void k_mlp(const float* __restrict__ w1, const float* __restrict__ b1,
                                             const float* __restrict__ w2, const float* __restrict__ b2,
                                             const float* __restrict__ w3, const float* __restrict__ b3,
                                             const float* __restrict__ w4, const float* __restrict__ b4,
                                             float* __restrict__ out, int n) {
    __shared__ float v[128], u[128];
    __shared__ float red[4];
    int t = threadIdx.x;
    v[t] = g_pool[t] / (float)n;
    __syncthreads();

    float acc = b1[t];
    for (int k = 0; k < 128; k++) acc += v[k] * w1[k * 128 + t];
    u[t] = fmaxf(acc, 0.f);
    __syncthreads();

    acc = b2[t];
    for (int k = 0; k < 128; k++) acc += u[k] * w2[k * 128 + t];
    v[t] = acc;
    __syncthreads();

    acc = b3[t];
    for (int k = 0; k < 128; k++) acc += v[k] * w3[k * 128 + t];
    u[t] = fmaxf(acc, 0.f);
    __syncthreads();

    float p = u[t] * w4[t];
#pragma unroll
    for (int o = 16; o; o >>= 1) p += __shfl_down_sync(0xffffffffu, p, o);
    if ((t & 31) == 0) red[t >> 5] = p;
    __syncthreads();
    if (t == 0) {
        float s = red[0] + red[1] + red[2] + red[3] + b4[0];
        out[0] = 1.f / (1.f + expf(-s));
    }
}

// ---------------- launch ----------------
extern "C" void kernel_launch(void* const* d_in, const int* in_sizes, int n_in,
                              void* d_out, int out_size) {
    const float* x    = (const float*)d_in[0];
    const int*   ei   = (const int*)d_in[1];
    const float* c1w  = (const float*)d_in[2];
    const float* c1b  = (const float*)d_in[3];
    const float* c2w  = (const float*)d_in[4];
    const float* c2b  = (const float*)d_in[5];
    const float* f1w1 = (const float*)d_in[6];
    const float* f1b1 = (const float*)d_in[7];
    const float* f1w2 = (const float*)d_in[8];
    const float* f1b2 = (const float*)d_in[9];
    const float* f2w1 = (const float*)d_in[10];
    const float* f2b1 = (const float*)d_in[11];
    const float* f2w2 = (const float*)d_in[12];
    const float* f2b2 = (const float*)d_in[13];

    int n = in_sizes[0] / F;
    int E = in_sizes[1] / 2;
    const int* src = ei;
    const int* dst = ei + E;

    float* h   = nullptr;
    float* agg = nullptr;
    cudaGetSymbolAddress((void**)&h,   g_h);
    cudaGetSymbolAddress((void**)&agg, g_agg);

    int tb = 256;
    int gN    = (n + tb - 1) / tb;
    int gE    = (E + tb - 1) / tb;
    int gGemm = (n + 127) / 128;
    int gAgg  = (n * 32 + tb - 1) / tb;   // one warp per node
    int gPool = (n + 63) / 64;

    // graph prep: degree buckets + dinv
    k_init<<<gN, tb>>>(n);
    k_fill<<<gE, tb>>>(src, dst, E);
    k_dinv<<<gN, tb>>>(n);

    // conv1: h = (x@W1)*dinv ; agg = relu(dinv*(gather-sum + self) + b1)
    k_gemm_tc<<<gGemm, 256>>>(x, c1w, h, n);
    k_aggregate<<<gAgg, tb>>>(c1b, agg, n);

    // conv2
    k_gemm_tc<<<gGemm, 256>>>(agg, c2w, h, n);
    k_aggregate<<<gAgg, tb>>>(c2b, agg, n);

    // pool + MLP tail
    k_pool<<<gPool, 128>>>(n);
    k_mlp<<<1, 128>>>(f1w1, f1b1, f1w2, f1b2, f2w1, f2b1, f2w2, f2b2,
                      (float*)d_out, n);
}

// round 4
// speedup vs baseline: 2.4726x; 1.0819x over previous
#include <cuda_runtime.h>
#include <cuda_bf16.h>
#include <math.h>
#include <stdint.h>

#define F 128
#define MAXN 50176    // >= 50000
#define CAP 128       // max in-degree bucket (Poisson(16): P(deg>128) ~ 0)

// ---------------- scratch (no allocations allowed) ----------------
__device__ __nv_bfloat162 g_hb[(size_t)MAXN * 64]; // GEMM out * dinv[row], bf16 (128 feats = 64 pairs)
__device__ float g_agg[(size_t)MAXN * F];          // layer-1 output (fp32, GEMM2 input)
__device__ float g_dinv[MAXN];
__device__ int   g_cnt[MAXN];                      // in-degree (excl. self loop)
__device__ int   g_csr[(size_t)MAXN * CAP];        // bucketed neighbor lists (src ids)
__device__ float g_pool[F];

// ---------------- init: zero counts + pool ----------------
__global__ void k_init(int n) {
    int i = blockIdx.x * blockDim.x + threadIdx.x;
    if (i < n) g_cnt[i] = 0;
    if (i < F) g_pool[i] = 0.f;
}

// ---------------- CSR bucket fill ----------------
__global__ void k_fill(const int* __restrict__ src, const int* __restrict__ dst, int E) {
    int e = blockIdx.x * blockDim.x + threadIdx.x;
    if (e >= E) return;
    int d = dst[e];
    int pos = atomicAdd(&g_cnt[d], 1);
    if (pos < CAP) g_csr[(size_t)d * CAP + pos] = src[e];
}

// ---------------- dinv = rsqrt(deg + 1) ----------------
__global__ void k_dinv(int n) {
    int i = blockIdx.x * blockDim.x + threadIdx.x;
    if (i < n) g_dinv[i] = rsqrtf((float)g_cnt[i] + 1.0f);
}

// ---------------- cp.async helpers ----------------
__device__ __forceinline__ void cp16(void* s, const void* g) {
    uint32_t sa = (uint32_t)__cvta_generic_to_shared(s);
    asm volatile("cp.async.cg.shared.global [%0], [%1], 16;" :: "r"(sa), "l"(g));
}
__device__ __forceinline__ void cp_commit() { asm volatile("cp.async.commit_group;" ::: "memory"); }
template<int N> __device__ __forceinline__ void cp_wait() {
    asm volatile("cp.async.wait_group %0;" :: "n"(N) : "memory");
}

// ---------------- tf32 tensor-core GEMM, cp.async double-buffered ----------------
// C_bf16[n,128] = (A[n,128] @ W[128,128]) * dinv[row]
// 128x128 block tile, 256 threads = 8 warps (4 row x 2 col), warp tile 32x64,
// mma.sync.m16n8k8 tf32 (raw fp32 bits, HW-truncated). K tiled by 32, 2 smem stages.
// sA stride 36 (mod32=4 -> a-frag banks 4g+c distinct); sW stride 136 (mod32=8 -> 8c+g distinct).
#define SA_STRIDE 36
#define SW_STRIDE 136
#define SA_FLOATS (128 * SA_STRIDE)
#define SW_FLOATS (32 * SW_STRIDE)
#define GEMM_SMEM ((2 * (SA_FLOATS + SW_FLOATS)) * 4)

__global__ __launch_bounds__(256) void k_gemm_tc(const float* __restrict__ A,
                                                 const float* __restrict__ W,
                                                 __nv_bfloat162* __restrict__ C, int n) {
    extern __shared__ float smem[];
    float* sAb[2] = { smem, smem + SA_FLOATS };
    float* sWb[2] = { smem + 2 * SA_FLOATS, smem + 2 * SA_FLOATS + SW_FLOATS };

    const int t    = threadIdx.x;
    const int lane = t & 31;
    const int w    = t >> 5;
    const int wr   = w & 3;          // warp row (0..3) -> 32 rows each
    const int wc   = w >> 2;         // warp col (0..1) -> 64 cols each
    const int g    = lane >> 2;      // groupID (0..7)
    const int c    = lane & 3;       // threadID_in_group (0..3)
    const int blockRow = blockIdx.x * 128;

    // per-thread load coords
    const int arow = t >> 1;                 // with j-offset below: rows 0..127
    // A: 1024 float4s / 256 threads = 4 each ; W likewise
    float d[2][8][4];
#pragma unroll
    for (int mt = 0; mt < 2; mt++)
#pragma unroll
        for (int nt = 0; nt < 8; nt++)
#pragma unroll
            for (int i = 0; i < 4; i++) d[mt][nt][i] = 0.f;

    (void)arow;

    auto load_stage = [&](int s, int kt) {
#pragma unroll
        for (int j = 0; j < 4; j++) {
            int idx = t + 256 * j;           // 0..1023
            int row = idx >> 3;              // 0..127
            int kq  = idx & 7;               // float4 within 32-k tile
            int gr  = blockRow + row; if (gr > n - 1) gr = n - 1;   // clamp (epilogue guards)
            cp16(sAb[s] + row * SA_STRIDE + kq * 4,
                 A + (size_t)gr * 128 + kt * 32 + kq * 4);
        }
#pragma unroll
        for (int j = 0; j < 4; j++) {
            int idx = t + 256 * j;
            int n4  = idx & 31;
            int k   = idx >> 5;
            cp16(sWb[s] + k * SW_STRIDE + n4 * 4,
                 W + (size_t)(kt * 32 + k) * 128 + n4 * 4);
        }
        cp_commit();
    };

    load_stage(0, 0);

    for (int kt = 0; kt < 4; kt++) {
        if (kt + 1 < 4) { load_stage((kt + 1) & 1, kt + 1); cp_wait<1>(); }
        else            { cp_wait<0>(); }
        __syncthreads();

        const uint32_t* sAu = (const uint32_t*)sAb[kt & 1];
        const uint32_t* sWu = (const uint32_t*)sWb[kt & 1];

#pragma unroll
        for (int kk = 0; kk < 4; kk++) {    // 4 ksteps of 8 within the 32-k tile
            uint32_t a[2][4];
#pragma unroll
            for (int mt = 0; mt < 2; mt++) {
                int r0 = wr * 32 + mt * 16;
                a[mt][0] = sAu[(r0 + g)     * SA_STRIDE + kk * 8 + c];
                a[mt][1] = sAu[(r0 + g + 8) * SA_STRIDE + kk * 8 + c];
                a[mt][2] = sAu[(r0 + g)     * SA_STRIDE + kk * 8 + c + 4];
                a[mt][3] = sAu[(r0 + g + 8) * SA_STRIDE + kk * 8 + c + 4];
            }
            uint32_t b[8][2];
#pragma unroll
            for (int nt = 0; nt < 8; nt++) {
                int n0 = wc * 64 + nt * 8;
                b[nt][0] = sWu[(kk * 8 + c)     * SW_STRIDE + n0 + g];
                b[nt][1] = sWu[(kk * 8 + c + 4) * SW_STRIDE + n0 + g];
            }
#pragma unroll
            for (int mt = 0; mt < 2; mt++)
#pragma unroll
                for (int nt = 0; nt < 8; nt++) {
                    asm volatile(
                        "mma.sync.aligned.m16n8k8.row.col.f32.tf32.tf32.f32 "
                        "{%0,%1,%2,%3}, {%4,%5,%6,%7}, {%8,%9}, {%0,%1,%2,%3};\n"
                        : "+f"(d[mt][nt][0]), "+f"(d[mt][nt][1]),
                          "+f"(d[mt][nt][2]), "+f"(d[mt][nt][3])
                        : "r"(a[mt][0]), "r"(a[mt][1]), "r"(a[mt][2]), "r"(a[mt][3]),
                          "r"(b[nt][0]), "r"(b[nt][1]));
                }
        }
        __syncthreads();
    }

    // ---- epilogue: scale by dinv[row], convert to bf16x2, store ----
#pragma unroll
    for (int mt = 0; mt < 2; mt++) {
        int rowA = blockRow + wr * 32 + mt * 16 + g;
        int rowB = rowA + 8;
        float dA = (rowA < n) ? g_dinv[rowA] : 0.f;
        float dB = (rowB < n) ? g_dinv[rowB] : 0.f;
#pragma unroll
        for (int nt = 0; nt < 8; nt++) {
            int p = wc * 32 + nt * 4 + c;      // bf16x2 index within row
            if (rowA < n)
                C[(size_t)rowA * 64 + p] = __floats2bfloat162_rn(d[mt][nt][0] * dA, d[mt][nt][1] * dA);
            if (rowB < n)
                C[(size_t)rowB * 64 + p] = __floats2bfloat162_rn(d[mt][nt][2] * dB, d[mt][nt][3] * dB);
        }
    }
}

// ---------------- gather helpers ----------------
__device__ __forceinline__ void acc_row(float4& acc, const uint2* hb, int row, int lane) {
    uint2 u = hb[(size_t)row * 32 + lane];
    __nv_bfloat162 p0 = *(__nv_bfloat162*)&u.x;
    __nv_bfloat162 p1 = *(__nv_bfloat162*)&u.y;
    float2 f0 = __bfloat1622float2(p0);
    float2 f1 = __bfloat1622float2(p1);
    acc.x += f0.x; acc.y += f0.y; acc.z += f1.x; acc.w += f1.y;
}

// ---------------- layer-1 aggregate: write fp32 rows ----------------
// One warp per node; lane handles 4 feats. out = relu(dinv*(Σ hb[s] + hb[d]) + b)
__global__ __launch_bounds__(256) void k_aggregate(const float* __restrict__ b,
                                                   float* __restrict__ out, int n) {
    int gid  = blockIdx.x * blockDim.x + threadIdx.x;
    int node = gid >> 5;
    int lane = gid & 31;
    if (node >= n) return;

    const uint2* hb = (const uint2*)g_hb;
    float4 acc = make_float4(0.f, 0.f, 0.f, 0.f);
    acc_row(acc, hb, node, lane);                 // self-loop
    int deg = g_cnt[node];
    if (deg > CAP) deg = CAP;
    const int* lst = g_csr + (size_t)node * CAP;

    int i = 0;
    for (; i + 4 <= deg; i += 4) {
        int s0 = lst[i], s1 = lst[i + 1], s2 = lst[i + 2], s3 = lst[i + 3];
        acc_row(acc, hb, s0, lane);
        acc_row(acc, hb, s1, lane);
        acc_row(acc, hb, s2, lane);
        acc_row(acc, hb, s3, lane);
    }
    for (; i < deg; i++) acc_row(acc, hb, lst[i], lane);

    float di = g_dinv[node];
    float4 bb = ((const float4*)b)[lane];
    acc.x = fmaxf(acc.x * di + bb.x, 0.f);
    acc.y = fmaxf(acc.y * di + bb.y, 0.f);
    acc.z = fmaxf(acc.z * di + bb.z, 0.f);
    acc.w = fmaxf(acc.w * di + bb.w, 0.f);
    ((float4*)out)[(size_t)node * 32 + lane] = acc;
}

// ---------------- layer-2 aggregate fused with mean-pool (no row write) ----------------
__global__ __launch_bounds__(256) void k_aggregate_pool(const float* __restrict__ b, int n) {
    __shared__ float sred[8 * 128];
    int lane = threadIdx.x & 31;
    int w    = threadIdx.x >> 5;
    const uint2* hb = (const uint2*)g_hb;
    float4 bb = ((const float4*)b)[lane];

    float4 pacc = make_float4(0.f, 0.f, 0.f, 0.f);
    for (int node = blockIdx.x * 8 + w; node < n; node += gridDim.x * 8) {
        float4 acc = make_float4(0.f, 0.f, 0.f, 0.f);
        acc_row(acc, hb, node, lane);
        int deg = g_cnt[node];
        if (deg > CAP) deg = CAP;
        const int* lst = g_csr + (size_t)node * CAP;
        int i = 0;
        for (; i + 4 <= deg; i += 4) {
            int s0 = lst[i], s1 = lst[i + 1], s2 = lst[i + 2], s3 = lst[i + 3];
            acc_row(acc, hb, s0, lane);
            acc_row(acc, hb, s1, lane);
            acc_row(acc, hb, s2, lane);
            acc_row(acc, hb, s3, lane);
        }
        for (; i < deg; i++) acc_row(acc, hb, lst[i], lane);
        float di = g_dinv[node];
        pacc.x += fmaxf(acc.x * di + bb.x, 0.f);
        pacc.y += fmaxf(acc.y * di + bb.y, 0.f);
        pacc.z += fmaxf(acc.z * di + bb.z, 0.f);
        pacc.w += fmaxf(acc.w * di + bb.w, 0.f);
    }
    *(float4*)(sred + w * 128 + lane * 4) = pacc;
    __syncthreads();
    int t = threadIdx.x;
    if (t < 128) {
        float s = 0.f;
#pragma unroll
        for (int wi = 0; wi < 8; wi++) s += sred[wi * 128 + t];
        atomicAdd(&g_pool[t], s);
    }
}

// ---------------- MLP tail (single block) ----------------
__global__ __launch_bounds__(128) void k_mlp(const float* __restrict__ w1, const float* __restrict__ b1,
                                             const float* __restrict__ w2, const float* __restrict__ b2,
                                             const float* __restrict__ w3, const float* __restrict__ b3,
                                             const float* __restrict__ w4, const float* __restrict__ b4,
                                             float* __restrict__ out, int n) {
    __shared__ float v[128], u[128];
    __shared__ float red[4];
    int t = threadIdx.x;
    v[t] = g_pool[t] / (float)n;
    __syncthreads();

    float acc = b1[t];
    for (int k = 0; k < 128; k++) acc += v[k] * w1[k * 128 + t];
    u[t] = fmaxf(acc, 0.f);
    __syncthreads();

    acc = b2[t];
    for (int k = 0; k < 128; k++) acc += u[k] * w2[k * 128 + t];
    v[t] = acc;
    __syncthreads();

    acc = b3[t];
    for (int k = 0; k < 128; k++) acc += v[k] * w3[k * 128 + t];
    u[t] = fmaxf(acc, 0.f);
    __syncthreads();

    float p = u[t] * w4[t];
#pragma unroll
    for (int o = 16; o; o >>= 1) p += __shfl_down_sync(0xffffffffu, p, o);
    if ((t & 31) == 0) red[t >> 5] = p;
    __syncthreads();
    if (t == 0) {
        float s = red[0] + red[1] + red[2] + red[3] + b4[0];
        out[0] = 1.f / (1.f + expf(-s));
    }
}

// ---------------- launch ----------------
extern "C" void kernel_launch(void* const* d_in, const int* in_sizes, int n_in,
                              void* d_out, int out_size) {
    const float* x    = (const float*)d_in[0];
    const int*   ei   = (const int*)d_in[1];
    const float* c1w  = (const float*)d_in[2];
    const float* c1b  = (const float*)d_in[3];
    const float* c2w  = (const float*)d_in[4];
    const float* c2b  = (const float*)d_in[5];
    const float* f1w1 = (const float*)d_in[6];
    const float* f1b1 = (const float*)d_in[7];
    const float* f1w2 = (const float*)d_in[8];
    const float* f1b2 = (const float*)d_in[9];
    const float* f2w1 = (const float*)d_in[10];
    const float* f2b1 = (const float*)d_in[11];
    const float* f2w2 = (const float*)d_in[12];
    const float* f2b2 = (const float*)d_in[13];

    int n = in_sizes[0] / F;
    int E = in_sizes[1] / 2;
    const int* src = ei;
    const int* dst = ei + E;

    __nv_bfloat162* hb = nullptr;
    float* agg = nullptr;
    cudaGetSymbolAddress((void**)&hb,  g_hb);
    cudaGetSymbolAddress((void**)&agg, g_agg);

    static bool attrSet = false;
    if (!attrSet) {
        cudaFuncSetAttribute(k_gemm_tc, cudaFuncAttributeMaxDynamicSharedMemorySize, GEMM_SMEM);
        attrSet = true;
    }

    int tb = 256;
    int gN    = (n + tb - 1) / tb;
    int gE    = (E + tb - 1) / tb;
    int gGemm = (n + 127) / 128;
    int gAgg  = (n * 32 + tb - 1) / tb;   // one warp per node
    int gAgg2 = 592;                       // grid-stride, 148 SMs * 4

    // graph prep: degree buckets + dinv
    k_init<<<gN, tb>>>(n);
    k_fill<<<gE, tb>>>(src, dst, E);
    k_dinv<<<gN, tb>>>(n);

    // conv1: hb = bf16((x@W1)*dinv) ; agg = relu(dinv*(gather+self) + b1)
    k_gemm_tc<<<gGemm, 256, GEMM_SMEM>>>(x, c1w, hb, n);
    k_aggregate<<<gAgg, tb>>>(c1b, agg, n);

    // conv2: hb = bf16((agg@W2)*dinv) ; fused aggregate + mean pool
    k_gemm_tc<<<gGemm, 256, GEMM_SMEM>>>(agg, c2w, hb, n);
    k_aggregate_pool<<<gAgg2, tb>>>(c2b, n);

    // MLP tail
    k_mlp<<<1, 128>>>(f1w1, f1b1, f1w2, f1b2, f2w1, f2b1, f2w2, f2b2,
                      (float*)d_out, n);
}

// round 5
// speedup vs baseline: 2.7912x; 1.1288x over previous
#include <cuda_runtime.h>
#include <cuda_bf16.h>
#include <math.h>
#include <stdint.h>

#define F 128
#define MAXN 50176    // >= 50000
#define CAP 128       // max in-degree bucket (Poisson(16): P(deg>128) ~ 0)

// ---------------- scratch (no allocations allowed) ----------------
__device__ __nv_bfloat162 g_hb[(size_t)MAXN * 64];   // GEMM out * dinv[row], bf16 pairs
__device__ __nv_bfloat162 g_aggb[(size_t)MAXN * 64]; // layer-1 output, bf16 pairs (GEMM2 input)
__device__ __nv_bfloat16  g_wb1[128 * 128];          // W1 transposed [n][k] bf16
__device__ __nv_bfloat16  g_wb2[128 * 128];          // W2 transposed [n][k] bf16
__device__ float g_dinv[MAXN];
__device__ int   g_cnt[MAXN];
__device__ int   g_csr[(size_t)MAXN * CAP];
__device__ float g_pool[F];

// ---------------- init: zero counts + pool ----------------
__global__ void k_init(int n) {
    int i = blockIdx.x * blockDim.x + threadIdx.x;
    if (i < n) g_cnt[i] = 0;
    if (i < F) g_pool[i] = 0.f;
}

// ---------------- CSR bucket fill ----------------
__global__ void k_fill(const int* __restrict__ src, const int* __restrict__ dst, int E) {
    int e = blockIdx.x * blockDim.x + threadIdx.x;
    if (e >= E) return;
    int d = dst[e];
    int pos = atomicAdd(&g_cnt[d], 1);
    if (pos < CAP) g_csr[(size_t)d * CAP + pos] = src[e];
}

// ---------------- dinv = rsqrt(deg + 1) ----------------
__global__ void k_dinv(int n) {
    int i = blockIdx.x * blockDim.x + threadIdx.x;
    if (i < n) g_dinv[i] = rsqrtf((float)g_cnt[i] + 1.0f);
}

// ---------------- weight prep: transpose [k][n] fp32 -> [n][k] bf16 ----------------
__global__ void k_prepw(const float* __restrict__ w1, const float* __restrict__ w2) {
    int i = blockIdx.x * blockDim.x + threadIdx.x;   // 0..16383
    if (i >= 16384) return;
    int nn = i >> 7, kk = i & 127;
    g_wb1[i] = __float2bfloat16(w1[kk * 128 + nn]);
    g_wb2[i] = __float2bfloat16(w2[kk * 128 + nn]);
}

// ---------------- cp.async helpers ----------------
__device__ __forceinline__ void cp16(void* s, const void* g) {
    uint32_t sa = (uint32_t)__cvta_generic_to_shared(s);
    asm volatile("cp.async.cg.shared.global [%0], [%1], 16;" :: "r"(sa), "l"(g));
}
__device__ __forceinline__ void cp_commit() { asm volatile("cp.async.commit_group;" ::: "memory"); }
template<int N> __device__ __forceinline__ void cp_wait() {
    asm volatile("cp.async.wait_group %0;" :: "n"(N) : "memory");
}

// ---------------- bf16 tensor-core GEMM (whole-K resident) ----------------
// C_bf16[n,128] = (A[n,128] @ W[128,128]) * dinv[row]
// 128x128 block tile, 256 threads = 8 warps (4x2), warp tile 32x64,
// mma.sync.m16n8k16 bf16. Full K=128 staged once: sA 128x136 bf16, sW 128x136 bf16 ([n][k]).
// Row stride 68 words -> frag-load bank = (4g + c) mod 32, all 32 lanes distinct.
#define KP_WORDS 68                      // 136 bf16 per padded row
#define GEMM_SMEM (2 * 128 * KP_WORDS * 4)

template<bool BF16IN>
__global__ __launch_bounds__(256) void k_gemm_bf16(const void* __restrict__ Aptr,
                                                   const __nv_bfloat16* __restrict__ Wb,
                                                   __nv_bfloat162* __restrict__ C, int n) {
    extern __shared__ uint32_t smem[];
    uint32_t* sA = smem;
    uint32_t* sW = smem + 128 * KP_WORDS;

    const int t    = threadIdx.x;
    const int lane = t & 31;
    const int w    = t >> 5;
    const int wr   = w & 3;          // warp row -> 32 rows
    const int wc   = w >> 2;         // warp col -> 64 cols
    const int g    = lane >> 2;
    const int c    = lane & 3;
    const int blockRow = blockIdx.x * 128;

    // ---- stage W: 128 rows x 256B via cp.async ----
#pragma unroll
    for (int j = 0; j < 8; j++) {
        int idx = t + 256 * j;           // 0..2047
        int row = idx >> 4;
        int ch  = idx & 15;
        cp16((char*)sW + row * 272 + ch * 16, (const char*)Wb + row * 256 + ch * 16);
    }
    // ---- stage A ----
    if (BF16IN) {
#pragma unroll
        for (int j = 0; j < 8; j++) {
            int idx = t + 256 * j;
            int row = idx >> 4;
            int ch  = idx & 15;
            int gr  = blockRow + row; if (gr > n - 1) gr = n - 1;
            cp16((char*)sA + row * 272 + ch * 16, (const char*)Aptr + (size_t)gr * 256 + ch * 16);
        }
        cp_commit();
        cp_wait<0>();
    } else {
        cp_commit();
        const float* Af = (const float*)Aptr;
#pragma unroll
        for (int j = 0; j < 16; j++) {
            int idx = t + 256 * j;           // 0..4095
            int row = idx >> 5;
            int q   = idx & 31;              // float4 index
            int gr  = blockRow + row; if (gr > n - 1) gr = n - 1;
            float4 v = __ldg((const float4*)(Af + (size_t)gr * 128 + q * 4));
            __nv_bfloat162 p0 = __floats2bfloat162_rn(v.x, v.y);
            __nv_bfloat162 p1 = __floats2bfloat162_rn(v.z, v.w);
            uint2 u = make_uint2(*(uint32_t*)&p0, *(uint32_t*)&p1);
            *(uint2*)((char*)sA + row * 272 + q * 8) = u;
        }
        cp_wait<0>();
    }
    __syncthreads();

    float d[2][8][4];
#pragma unroll
    for (int mt = 0; mt < 2; mt++)
#pragma unroll
        for (int nt = 0; nt < 8; nt++)
#pragma unroll
            for (int i = 0; i < 4; i++) d[mt][nt][i] = 0.f;

#pragma unroll
    for (int ks = 0; ks < 8; ks++) {         // 8 ksteps of 16
        uint32_t a[2][4];
#pragma unroll
        for (int mt = 0; mt < 2; mt++) {
            int m0 = wr * 32 + mt * 16;
            a[mt][0] = sA[(m0 + g)     * KP_WORDS + ks * 8 + c];
            a[mt][1] = sA[(m0 + g + 8) * KP_WORDS + ks * 8 + c];
            a[mt][2] = sA[(m0 + g)     * KP_WORDS + ks * 8 + c + 4];
            a[mt][3] = sA[(m0 + g + 8) * KP_WORDS + ks * 8 + c + 4];
        }
        uint32_t b[8][2];
#pragma unroll
        for (int nt = 0; nt < 8; nt++) {
            int n0 = wc * 64 + nt * 8;
            b[nt][0] = sW[(n0 + g) * KP_WORDS + ks * 8 + c];
            b[nt][1] = sW[(n0 + g) * KP_WORDS + ks * 8 + c + 4];
        }
#pragma unroll
        for (int mt = 0; mt < 2; mt++)
#pragma unroll
            for (int nt = 0; nt < 8; nt++) {
                asm volatile(
                    "mma.sync.aligned.m16n8k16.row.col.f32.bf16.bf16.f32 "
                    "{%0,%1,%2,%3}, {%4,%5,%6,%7}, {%8,%9}, {%0,%1,%2,%3};\n"
                    : "+f"(d[mt][nt][0]), "+f"(d[mt][nt][1]),
                      "+f"(d[mt][nt][2]), "+f"(d[mt][nt][3])
                    : "r"(a[mt][0]), "r"(a[mt][1]), "r"(a[mt][2]), "r"(a[mt][3]),
                      "r"(b[nt][0]), "r"(b[nt][1]));
            }
    }

    // ---- epilogue: scale by dinv[row], convert to bf16x2, store ----
#pragma unroll
    for (int mt = 0; mt < 2; mt++) {
        int rowA = blockRow + wr * 32 + mt * 16 + g;
        int rowB = rowA + 8;
        float dA = (rowA < n) ? g_dinv[rowA] : 0.f;
        float dB = (rowB < n) ? g_dinv[rowB] : 0.f;
#pragma unroll
        for (int nt = 0; nt < 8; nt++) {
            int p = wc * 32 + nt * 4 + c;
            if (rowA < n)
                C[(size_t)rowA * 64 + p] = __floats2bfloat162_rn(d[mt][nt][0] * dA, d[mt][nt][1] * dA);
            if (rowB < n)
                C[(size_t)rowB * 64 + p] = __floats2bfloat162_rn(d[mt][nt][2] * dB, d[mt][nt][3] * dB);
        }
    }
}

// ---------------- gather helper ----------------
__device__ __forceinline__ void acc_row(float4& acc, const uint2* hb, int row, int lane) {
    uint2 u = hb[(size_t)row * 32 + lane];
    __nv_bfloat162 p0 = *(__nv_bfloat162*)&u.x;
    __nv_bfloat162 p1 = *(__nv_bfloat162*)&u.y;
    float2 f0 = __bfloat1622float2(p0);
    float2 f1 = __bfloat1622float2(p1);
    acc.x += f0.x; acc.y += f0.y; acc.z += f1.x; acc.w += f1.y;
}

// ---------------- layer-1 aggregate: write bf16 rows ----------------
__global__ __launch_bounds__(256) void k_aggregate(const float* __restrict__ b,
                                                   __nv_bfloat162* __restrict__ out, int n) {
    int gid  = blockIdx.x * blockDim.x + threadIdx.x;
    int node = gid >> 5;
    int lane = gid & 31;
    if (node >= n) return;

    const uint2* hb = (const uint2*)g_hb;
    float4 acc = make_float4(0.f, 0.f, 0.f, 0.f);
    acc_row(acc, hb, node, lane);                 // self-loop
    int deg = g_cnt[node];
    if (deg > CAP) deg = CAP;
    const int* lst = g_csr + (size_t)node * CAP;

    int i = 0;
    for (; i + 4 <= deg; i += 4) {
        int s0 = lst[i], s1 = lst[i + 1], s2 = lst[i + 2], s3 = lst[i + 3];
        acc_row(acc, hb, s0, lane);
        acc_row(acc, hb, s1, lane);
        acc_row(acc, hb, s2, lane);
        acc_row(acc, hb, s3, lane);
    }
    for (; i < deg; i++) acc_row(acc, hb, lst[i], lane);

    float di = g_dinv[node];
    float4 bb = ((const float4*)b)[lane];
    float rx = fmaxf(acc.x * di + bb.x, 0.f);
    float ry = fmaxf(acc.y * di + bb.y, 0.f);
    float rz = fmaxf(acc.z * di + bb.z, 0.f);
    float rw = fmaxf(acc.w * di + bb.w, 0.f);
    __nv_bfloat162 o0 = __floats2bfloat162_rn(rx, ry);
    __nv_bfloat162 o1 = __floats2bfloat162_rn(rz, rw);
    *(uint2*)(out + (size_t)node * 64 + lane * 2) = make_uint2(*(uint32_t*)&o0, *(uint32_t*)&o1);
}

// ---------------- layer-2 aggregate fused with mean-pool ----------------
__global__ __launch_bounds__(256) void k_aggregate_pool(const float* __restrict__ b, int n) {
    __shared__ float sred[8 * 128];
    int lane = threadIdx.x & 31;
    int w    = threadIdx.x >> 5;
    const uint2* hb = (const uint2*)g_hb;
    float4 bb = ((const float4*)b)[lane];

    float4 pacc = make_float4(0.f, 0.f, 0.f, 0.f);
    for (int node = blockIdx.x * 8 + w; node < n; node += gridDim.x * 8) {
        float4 acc = make_float4(0.f, 0.f, 0.f, 0.f);
        acc_row(acc, hb, node, lane);
        int deg = g_cnt[node];
        if (deg > CAP) deg = CAP;
        const int* lst = g_csr + (size_t)node * CAP;
        int i = 0;
        for (; i + 4 <= deg; i += 4) {
            int s0 = lst[i], s1 = lst[i + 1], s2 = lst[i + 2], s3 = lst[i + 3];
            acc_row(acc, hb, s0, lane);
            acc_row(acc, hb, s1, lane);
            acc_row(acc, hb, s2, lane);
            acc_row(acc, hb, s3, lane);
        }
        for (; i < deg; i++) acc_row(acc, hb, lst[i], lane);
        float di = g_dinv[node];
        pacc.x += fmaxf(acc.x * di + bb.x, 0.f);
        pacc.y += fmaxf(acc.y * di + bb.y, 0.f);
        pacc.z += fmaxf(acc.z * di + bb.z, 0.f);
        pacc.w += fmaxf(acc.w * di + bb.w, 0.f);
    }
    *(float4*)(sred + w * 128 + lane * 4) = pacc;
    __syncthreads();
    int t = threadIdx.x;
    if (t < 128) {
        float s = 0.f;
#pragma unroll
        for (int wi = 0; wi < 8; wi++) s += sred[wi * 128 + t];
        atomicAdd(&g_pool[t], s);
    }
}

// ---------------- MLP tail (single block) ----------------
__global__ __launch_bounds__(128) void k_mlp(const float* __restrict__ w1, const float* __restrict__ b1,
                                             const float* __restrict__ w2, const float* __restrict__ b2,
                                             const float* __restrict__ w3, const float* __restrict__ b3,
                                             const float* __restrict__ w4, const float* __restrict__ b4,
                                             float* __restrict__ out, int n) {
    __shared__ float v[128], u[128];
    __shared__ float red[4];
    int t = threadIdx.x;
    v[t] = g_pool[t] / (float)n;
    __syncthreads();

    float acc = b1[t];
    for (int k = 0; k < 128; k++) acc += v[k] * w1[k * 128 + t];
    u[t] = fmaxf(acc, 0.f);
    __syncthreads();

    acc = b2[t];
    for (int k = 0; k < 128; k++) acc += u[k] * w2[k * 128 + t];
    v[t] = acc;
    __syncthreads();

    acc = b3[t];
    for (int k = 0; k < 128; k++) acc += v[k] * w3[k * 128 + t];
    u[t] = fmaxf(acc, 0.f);
    __syncthreads();

    float p = u[t] * w4[t];
#pragma unroll
    for (int o = 16; o; o >>= 1) p += __shfl_down_sync(0xffffffffu, p, o);
    if ((t & 31) == 0) red[t >> 5] = p;
    __syncthreads();
    if (t == 0) {
        float s = red[0] + red[1] + red[2] + red[3] + b4[0];
        out[0] = 1.f / (1.f + expf(-s));
    }
}

// ---------------- launch ----------------
extern "C" void kernel_launch(void* const* d_in, const int* in_sizes, int n_in,
                              void* d_out, int out_size) {
    const float* x    = (const float*)d_in[0];
    const int*   ei   = (const int*)d_in[1];
    const float* c1w  = (const float*)d_in[2];
    const float* c1b  = (const float*)d_in[3];
    const float* c2w  = (const float*)d_in[4];
    const float* c2b  = (const float*)d_in[5];
    const float* f1w1 = (const float*)d_in[6];
    const float* f1b1 = (const float*)d_in[7];
    const float* f1w2 = (const float*)d_in[8];
    const float* f1b2 = (const float*)d_in[9];
    const float* f2w1 = (const float*)d_in[10];
    const float* f2b1 = (const float*)d_in[11];
    const float* f2w2 = (const float*)d_in[12];
    const float* f2b2 = (const float*)d_in[13];

    int n = in_sizes[0] / F;
    int E = in_sizes[1] / 2;
    const int* src = ei;
    const int* dst = ei + E;

    __nv_bfloat162* hb   = nullptr;
    __nv_bfloat162* aggb = nullptr;
    __nv_bfloat16*  wb1  = nullptr;
    __nv_bfloat16*  wb2  = nullptr;
    cudaGetSymbolAddress((void**)&hb,   g_hb);
    cudaGetSymbolAddress((void**)&aggb, g_aggb);
    cudaGetSymbolAddress((void**)&wb1,  g_wb1);
    cudaGetSymbolAddress((void**)&wb2,  g_wb2);

    static bool attrSet = false;
    if (!attrSet) {
        cudaFuncSetAttribute(k_gemm_bf16<false>, cudaFuncAttributeMaxDynamicSharedMemorySize, GEMM_SMEM);
        cudaFuncSetAttribute(k_gemm_bf16<true>,  cudaFuncAttributeMaxDynamicSharedMemorySize, GEMM_SMEM);
        attrSet = true;
    }

    int tb = 256;
    int gN    = (n + tb - 1) / tb;
    int gE    = (E + tb - 1) / tb;
    int gGemm = (n + 127) / 128;
    int gAgg  = (n * 32 + tb - 1) / tb;
    int gAgg2 = 592;

    // graph prep + weight prep
    k_init<<<gN, tb>>>(n);
    k_fill<<<gE, tb>>>(src, dst, E);
    k_dinv<<<gN, tb>>>(n);
    k_prepw<<<64, 256>>>(c1w, c2w);

    // conv1: hb = bf16((x@W1)*dinv) ; aggb = bf16(relu(dinv*(gather+self) + b1))
    k_gemm_bf16<false><<<gGemm, 256, GEMM_SMEM>>>(x, wb1, hb, n);
    k_aggregate<<<gAgg, tb>>>(c1b, aggb, n);

    // conv2: hb = bf16((aggb@W2)*dinv) ; fused aggregate + mean pool
    k_gemm_bf16<true><<<gGemm, 256, GEMM_SMEM>>>(aggb, wb2, hb, n);
    k_aggregate_pool<<<gAgg2, tb>>>(c2b, n);

    // MLP tail
    k_mlp<<<1, 128>>>(f1w1, f1b1, f1w2, f1b2, f2w1, f2b1, f2w2, f2b2,
                      (float*)d_out, n);
}